// round 15
// baseline (speedup 1.0000x reference)
#include <cuda_runtime.h>
#include <cuda_bf16.h>
#include <cstdint>
#include <cfloat>

#define B_    64
#define H_    512
#define N_    16384
#define W_    64
#define DIN_  512
#define KDIM_ 1088
#define G4_   2048
#define KSPLIT_ 8
#define KPER_   136   // 1088/8

// d_out layout (floats)
#define OFF_Y   0
#define OFF_H   32768
#define OFF_C   65536
#define OFF_M   98304
#define OFF_WR  67207168
#define OFF_US  68255744
#define OFF_R   69304320

typedef unsigned long long u64;

// scratch
__device__ float g_zp[KSPLIT_ * B_ * G4_];
__device__ float g_qn[B_ * W_];
__device__ float g_a[B_ * W_];
__device__ float g_e[B_ * W_];
__device__ float g_alpha[B_];
__device__ float g_gamma[B_];
__device__ u64   g_simk[8192 * 4];  // per fused-block top-4 sim keys
__device__ u64   g_usk[512 * 5];    // (b*8+chunk) top-5 usage keys
__device__ float g_ypart[B_ * H_];  // y partial (h-portion of the dot)

__device__ __forceinline__ float sigmoidf_(float x) { return 1.0f / (1.0f + expf(-x)); }

// ---- packed-key primitives (merge phase only) ----
__device__ __forceinline__ u64 umax64(u64 a, u64 b) { return a > b ? a : b; }
__device__ __forceinline__ u64 umin64(u64 a, u64 b) { return a < b ? a : b; }
#define CE_DESC(x, y) { u64 _mx = umax64(x, y); u64 _mn = umin64(x, y); (x) = _mx; (y) = _mn; }

__device__ __forceinline__ u64 pack_key(float v, int n) {
    unsigned vb = __float_as_uint(v);
    vb = (vb & 0x80000000u) ? ~vb : (vb | 0x80000000u);
    return ((u64)vb << 32) | (unsigned)(0xFFFFFFFFu - (unsigned)n);
}
__device__ __forceinline__ float key_val(u64 k) {
    unsigned vb = (unsigned)(k >> 32);
    vb = (vb & 0x80000000u) ? (vb ^ 0x80000000u) : ~vb;
    return __uint_as_float(vb);
}
__device__ __forceinline__ int key_idx(u64 k) {
    return (int)(0xFFFFFFFFu - (unsigned)(k & 0xFFFFFFFFull));
}

__device__ __forceinline__ void bmerge4(u64* a, const u64* brev) {
    a[0] = umax64(a[0], brev[0]); a[1] = umax64(a[1], brev[1]);
    a[2] = umax64(a[2], brev[2]); a[3] = umax64(a[3], brev[3]);
    CE_DESC(a[0], a[2]); CE_DESC(a[1], a[3]);
    CE_DESC(a[0], a[1]); CE_DESC(a[2], a[3]);
}

__device__ __forceinline__ void bmerge5(u64* a, const u64* brev) {
#pragma unroll
    for (int j = 0; j < 5; j++) a[j] = umax64(a[j], brev[j]);
#pragma unroll
    for (int i = 1; i < 5; i++)
#pragma unroll
        for (int j = i; j > 0; j--)
            CE_DESC(a[j-1], a[j]);
}

template<int MAXOFF>
__device__ __forceinline__ void warp_bmerge4(u64* a) {
#pragma unroll
    for (int off = MAXOFF; off > 0; off >>= 1) {
        u64 b[4];
#pragma unroll
        for (int j = 0; j < 4; j++) b[j] = __shfl_down_sync(0xffffffffu, a[3-j], off);
        bmerge4(a, b);
    }
}

template<int MAXOFF>
__device__ __forceinline__ void warp_bmerge5(u64* a) {
#pragma unroll
    for (int off = MAXOFF; off > 0; off >>= 1) {
        u64 b[5];
#pragma unroll
        for (int j = 0; j < 5; j++) b[j] = __shfl_down_sync(0xffffffffu, a[4-j], off);
        bmerge5(a, b);
    }
}

// ---- fp32 scan primitives ----
__device__ __forceinline__ void insf4(float* bv, int* bi, float v, int n) {
    if (v > bv[3] || (v == bv[3] && n < bi[3])) {
        bv[3] = v; bi[3] = n;
        if (bv[3] > bv[2] || (bv[3] == bv[2] && bi[3] < bi[2])) {
            float tv = bv[2]; bv[2] = bv[3]; bv[3] = tv;
            int ti = bi[2]; bi[2] = bi[3]; bi[3] = ti;
        }
        if (bv[2] > bv[1] || (bv[2] == bv[1] && bi[2] < bi[1])) {
            float tv = bv[1]; bv[1] = bv[2]; bv[2] = tv;
            int ti = bi[1]; bi[1] = bi[2]; bi[2] = ti;
        }
        if (bv[1] > bv[0] || (bv[1] == bv[0] && bi[1] < bi[0])) {
            float tv = bv[0]; bv[0] = bv[1]; bv[1] = tv;
            int ti = bi[0]; bi[0] = bi[1]; bi[1] = ti;
        }
    }
}

__device__ __forceinline__ void insf5(float* bv, int* bi, float v, int n) {
    if (v > bv[4] || (v == bv[4] && n < bi[4])) {
        bv[4] = v; bi[4] = n;
        if (bv[4] > bv[3] || (bv[4] == bv[3] && bi[4] < bi[3])) {
            float tv = bv[3]; bv[3] = bv[4]; bv[4] = tv;
            int ti = bi[3]; bi[3] = bi[4]; bi[4] = ti;
        }
        if (bv[3] > bv[2] || (bv[3] == bv[2] && bi[3] < bi[2])) {
            float tv = bv[2]; bv[2] = bv[3]; bv[3] = tv;
            int ti = bi[2]; bi[2] = bi[3]; bi[3] = ti;
        }
        if (bv[2] > bv[1] || (bv[2] == bv[1] && bi[2] < bi[1])) {
            float tv = bv[1]; bv[1] = bv[2]; bv[2] = tv;
            int ti = bi[1]; bi[1] = bi[2]; bi[2] = ti;
        }
        if (bv[1] > bv[0] || (bv[1] == bv[0] && bi[1] < bi[0])) {
            float tv = bv[0]; bv[0] = bv[1]; bv[1] = tv;
            int ti = bi[0]; bi[0] = bi[1]; bi[1] = ti;
        }
    }
}

// ---------------------------------------------------------------------------
// K1: z partials, software-pipelined. grid = 32 jt x 8 ks = 256 blocks, 256 thr.
// Double-buffered smem; chunk c+1 prefetched into regs while computing c.
// ---------------------------------------------------------------------------
__global__ void k_gemm_z(const float* __restrict__ inp, const float* __restrict__ rprev,
                         const float* __restrict__ hprev, const float* __restrict__ Wk,
                         const float* __restrict__ Uk) {
    __shared__ __align__(16) float Xs[2][8][64];
    __shared__ __align__(16) float Ws[2][8][64];
    const int jt = blockIdx.x & 31;
    const int ks = blockIdx.x >> 5;
    const int j0 = jt * 64;
    const int kbase = ks * KPER_;
    const int t = threadIdx.x;
    const int tj = t & 15;
    const int tb = t >> 4;

    // per-thread load coords (2 X elems + 2 W elems per chunk)
    const int xb0 = t >> 3,        xk0 = t & 7;          // idx = t
    const int xb1 = (t + 256) >> 3, xk1 = (t + 256) & 7; // idx = t+256
    const int wk0 = t >> 6,        wj0 = t & 63;
    const int wk1 = (t + 256) >> 6, wj1 = (t + 256) & 63;

    auto loadX = [&](int kg, int b) -> float {
        if (kg < DIN_)           return inp[b * DIN_ + kg];
        else if (kg < DIN_ + W_) return rprev[b * W_ + (kg - DIN_)];
        else                     return hprev[b * H_ + (kg - DIN_ - W_)];
    };
    auto loadW = [&](int kg, int jj) -> float {
        return (kg < DIN_ + W_) ? Wk[kg * G4_ + j0 + jj]
                                : Uk[(kg - DIN_ - W_) * G4_ + j0 + jj];
    };

    float acc[4][4];
#pragma unroll
    for (int r = 0; r < 4; r++)
#pragma unroll
        for (int c = 0; c < 4; c++) acc[r][c] = 0.0f;

    // stage chunk 0
    {
        const int k0 = kbase;
        Xs[0][xk0][xb0] = loadX(k0 + xk0, xb0);
        Xs[0][xk1][xb1] = loadX(k0 + xk1, xb1);
        Ws[0][wk0][wj0] = loadW(k0 + wk0, wj0);
        Ws[0][wk1][wj1] = loadW(k0 + wk1, wj1);
    }
    __syncthreads();

    for (int cch = 0; cch < 17; cch++) {
        const int buf = cch & 1;
        float px0, px1, pw0, pw1;
        if (cch < 16) {
            const int k0 = kbase + (cch + 1) * 8;
            px0 = loadX(k0 + xk0, xb0);
            px1 = loadX(k0 + xk1, xb1);
            pw0 = loadW(k0 + wk0, wj0);
            pw1 = loadW(k0 + wk1, wj1);
        }
#pragma unroll
        for (int kk = 0; kk < 8; kk++) {
            float4 xv = *(const float4*)&Xs[buf][kk][tb * 4];
            float4 wv = *(const float4*)&Ws[buf][kk][tj * 4];
            float xr[4] = {xv.x, xv.y, xv.z, xv.w};
            float wc[4] = {wv.x, wv.y, wv.z, wv.w};
#pragma unroll
            for (int r = 0; r < 4; r++)
#pragma unroll
                for (int c = 0; c < 4; c++) acc[r][c] += xr[r] * wc[c];
        }
        if (cch < 16) {
            const int nb = buf ^ 1;
            Xs[nb][xk0][xb0] = px0;
            Xs[nb][xk1][xb1] = px1;
            Ws[nb][wk0][wj0] = pw0;
            Ws[nb][wk1][wj1] = pw1;
        }
        __syncthreads();
    }
#pragma unroll
    for (int r = 0; r < 4; r++) {
        float4 st = make_float4(acc[r][0], acc[r][1], acc[r][2], acc[r][3]);
        *(float4*)&g_zp[ks * (B_ * G4_) + (tb * 4 + r) * G4_ + j0 + tj * 4] = st;
    }
}

// ---------------------------------------------------------------------------
// K2: z reduce + gates + params (split-k2) + derive. grid=64, block=512
// ---------------------------------------------------------------------------
__global__ void k_hparams(const float* __restrict__ cprev, const float* __restrict__ bl,
                          const float* __restrict__ Wp, const float* __restrict__ bp,
                          float* __restrict__ h_out, float* __restrict__ c_out) {
    __shared__ float zz[G4_];
    __shared__ float sh[H_];
    __shared__ float sp[194];
    __shared__ float psums[2][256];
    __shared__ float ws[2];
    const int b = blockIdx.x, tid = threadIdx.x;

#pragma unroll
    for (int i = 0; i < 4; i++) {
        const int hh = tid + i * 512;
        float z = bl[hh];
#pragma unroll
        for (int ks = 0; ks < KSPLIT_; ks++)
            z += g_zp[ks * (B_ * G4_) + b * G4_ + hh];
        zz[hh] = z;
    }
    __syncthreads();

    {
        const int hh = tid;
        float ig = sigmoidf_(zz[hh]);
        float fg = sigmoidf_(zz[H_ + hh]);
        float og = sigmoidf_(zz[3 * H_ + hh]);
        float c  = fg * cprev[b * H_ + hh] + ig * tanhf(zz[2 * H_ + hh]);
        float h  = og * tanhf(c);
        c_out[b * H_ + hh] = c;
        h_out[b * H_ + hh] = h;
        sh[hh] = h;
    }
    __syncthreads();

    // params GEMM split-k2: kh = tid>>8, jj = tid&255
    {
        const int kh = tid >> 8;
        const int jj = tid & 255;
        if (jj < 194) {
            float acc = 0.0f;
            const int k0 = kh * 256, k1 = k0 + 256;
#pragma unroll 8
            for (int k = k0; k < k1; k++) acc += sh[k] * Wp[k * 194 + jj];
            psums[kh][jj] = acc;
        }
    }
    __syncthreads();
    if (tid < 194) sp[tid] = bp[tid] + psums[0][tid] + psums[1][tid];
    __syncthreads();

    if (tid < 64) {
        float q = sp[tid];
        float s = q * q;
#pragma unroll
        for (int off = 16; off > 0; off >>= 1) s += __shfl_down_sync(0xffffffffu, s, off);
        if ((tid & 31) == 0) ws[tid >> 5] = s;
    }
    __syncthreads();
    if (tid < 64) {
        float tot = ws[0] + ws[1];
        g_qn[b * W_ + tid] = sp[tid] * rsqrtf(fmaxf(tot, 1e-12f));
        g_a[b * W_ + tid]  = sp[W_ + tid];
        g_e[b * W_ + tid]  = sigmoidf_(sp[2 * W_ + tid]);
        if (tid == 0) {
            g_alpha[b] = sigmoidf_(sp[192]);
            g_gamma[b] = sigmoidf_(sp[193]);
        }
    }
}

// ---------------------------------------------------------------------------
// K3 (FUSED, frozen R11/R14 form)
// ---------------------------------------------------------------------------
__global__ void k_fused(const float* __restrict__ M, const float* __restrict__ wrp,
                        float* __restrict__ Mout) {
    const int b  = blockIdx.x >> 7;
    const int n0 = (blockIdx.x & 127) << 7;
    const int tid = threadIdx.x;
    __shared__ __align__(16) float se[W_], sa[W_], sq[W_];
    __shared__ __align__(16) float s_sim[128];
    __shared__ float s_ag;
    if (tid < W_) { se[tid] = g_e[b * W_ + tid]; sa[tid] = g_a[b * W_ + tid]; sq[tid] = g_qn[b * W_ + tid]; }
    if (tid == 0) s_ag = g_alpha[b] * g_gamma[b];
    __syncthreads();

    const int lane = tid & 31, warp = tid >> 5;
    const int half = lane >> 4, l16 = lane & 15;
    const int rbase = warp * 2 + half;
    const size_t browoff = (size_t)b * N_ + n0;

    float4 m[8];
    float wr[8];
#pragma unroll
    for (int i = 0; i < 8; i++)
        m[i] = __ldcs((const float4*)(M + (browoff + i * 16 + rbase) * W_) + l16);
#pragma unroll
    for (int i = 0; i < 8; i++)
        wr[i] = __ldg(wrp + browoff + i * 16 + rbase);

    const float4 e4 = *(const float4*)(se + l16 * 4);
    const float4 a4 = *(const float4*)(sa + l16 * 4);
    const float4 q4 = *(const float4*)(sq + l16 * 4);
    const float ag = s_ag;

#pragma unroll
    for (int i = 0; i < 8; i++) {
        float dot = m[i].x * q4.x + m[i].y * q4.y + m[i].z * q4.z + m[i].w * q4.w;
        float ss  = m[i].x * m[i].x + m[i].y * m[i].y + m[i].z * m[i].z + m[i].w * m[i].w;
#pragma unroll
        for (int off = 8; off > 0; off >>= 1) {
            dot += __shfl_down_sync(0xffffffffu, dot, off);
            ss  += __shfl_down_sync(0xffffffffu, ss,  off);
        }
        if (l16 == 0) s_sim[i * 16 + rbase] = dot * rsqrtf(fmaxf(ss, 1e-12f));

        const float ww = ag * wr[i];
        float4 o;
        o.x = m[i].x * (1.0f - ww * e4.x) + ww * a4.x;
        o.y = m[i].y * (1.0f - ww * e4.y) + ww * a4.y;
        o.z = m[i].z * (1.0f - ww * e4.z) + ww * a4.z;
        o.w = m[i].w * (1.0f - ww * e4.w) + ww * a4.w;
        __stcs((float4*)(Mout + (browoff + i * 16 + rbase) * W_) + l16, o);
    }
    __syncthreads();

    if (warp == 0) {
        float4 sv = ((const float4*)s_sim)[lane];
        float bv[4] = {-FLT_MAX, -FLT_MAX, -FLT_MAX, -FLT_MAX};
        int   bi[4] = {0x7FFFFFFF, 0x7FFFFFFF, 0x7FFFFFFF, 0x7FFFFFFF};
        const int nb = n0 + lane * 4;
        insf4(bv, bi, sv.x, nb + 0);
        insf4(bv, bi, sv.y, nb + 1);
        insf4(bv, bi, sv.z, nb + 2);
        insf4(bv, bi, sv.w, nb + 3);
        u64 a[4];
#pragma unroll
        for (int j = 0; j < 4; j++) a[j] = pack_key(bv[j], bi[j]);
        warp_bmerge4<16>(a);
        if (lane == 0) {
#pragma unroll
            for (int j = 0; j < 4; j++) g_simk[blockIdx.x * 4 + j] = a[j];
        }
    }
}

// ---------------------------------------------------------------------------
// K4 (side stream): usage top-5 + us/wr streams. grid=512, block=256.
// ---------------------------------------------------------------------------
__global__ void k_sel_us(const float* __restrict__ usprev,
                         float* __restrict__ wr_out, float* __restrict__ us_out) {
    const int tid = threadIdx.x;
    const int lane = tid & 31, warp = tid >> 5;
    const int b = blockIdx.x >> 3, chunk = blockIdx.x & 7;
    const int base = b * N_ + chunk * 2048;
    const float4* usb = (const float4*)(usprev + base);
    float4* uso = (float4*)(us_out + base);
    float4* wro = (float4*)(wr_out + base);
    const int nbase = chunk * 2048;

    float bv[5] = {-FLT_MAX, -FLT_MAX, -FLT_MAX, -FLT_MAX, -FLT_MAX};
    int   bi[5] = {0x7FFFFFFF, 0x7FFFFFFF, 0x7FFFFFFF, 0x7FFFFFFF, 0x7FFFFFFF};

    float4 v0 = __ldg(usb + tid);
    float4 v1 = __ldg(usb + 256 + tid);
    __stcs(uso + tid,       make_float4(v0.x + 1.f, v0.y + 1.f, v0.z + 1.f, v0.w + 1.f));
    __stcs(uso + 256 + tid, make_float4(v1.x + 1.f, v1.y + 1.f, v1.z + 1.f, v1.w + 1.f));
    __stcs(wro + tid,       make_float4(0.f, 0.f, 0.f, 0.f));
    __stcs(wro + 256 + tid, make_float4(0.f, 0.f, 0.f, 0.f));

    insf5(bv, bi, v0.x, nbase + tid * 4 + 0);
    insf5(bv, bi, v0.y, nbase + tid * 4 + 1);
    insf5(bv, bi, v0.z, nbase + tid * 4 + 2);
    insf5(bv, bi, v0.w, nbase + tid * 4 + 3);
    insf5(bv, bi, v1.x, nbase + 1024 + tid * 4 + 0);
    insf5(bv, bi, v1.y, nbase + 1024 + tid * 4 + 1);
    insf5(bv, bi, v1.z, nbase + 1024 + tid * 4 + 2);
    insf5(bv, bi, v1.w, nbase + 1024 + tid * 4 + 3);

    u64 a[5];
#pragma unroll
    for (int j = 0; j < 5; j++) a[j] = pack_key(bv[j], bi[j]);
    warp_bmerge5<16>(a);

    __shared__ u64 sw5[8][5];
    if (lane == 0) {
#pragma unroll
        for (int j = 0; j < 5; j++) sw5[warp][j] = a[j];
    }
    __syncthreads();
    if (warp == 0) {
        if (lane < 8) {
#pragma unroll
            for (int j = 0; j < 5; j++) a[j] = sw5[lane][j];
        } else {
#pragma unroll
            for (int j = 0; j < 5; j++) a[j] = 0ull;
        }
        warp_bmerge5<4>(a);
        if (lane == 0) {
#pragma unroll
            for (int j = 0; j < 5; j++) g_usk[blockIdx.x * 5 + j] = a[j];
        }
    }
}

// ---------------------------------------------------------------------------
// K5 (side stream, after hparams): y partial = bf + h @ Wf[0:512].
// ---------------------------------------------------------------------------
__global__ void k_ypart(const float* __restrict__ h, const float* __restrict__ Wf,
                        const float* __restrict__ bf) {
    __shared__ __align__(16) float xs[H_];
    __shared__ float psum[256];
    const int b = blockIdx.x >> 2;
    const int jt = blockIdx.x & 3;
    const int tid = threadIdx.x;

    xs[tid]       = h[b * H_ + tid];
    xs[tid + 256] = h[b * H_ + tid + 256];
    __syncthreads();

    const int jl = tid & 127;
    const int j = jt * 128 + jl;
    const int khalf = tid >> 7;
    float acc = 0.0f;
    const int k0 = khalf * 256, k1 = k0 + 256;
#pragma unroll 8
    for (int k = k0; k < k1; k++) acc += xs[k] * __ldg(Wf + k * H_ + j);
    psum[tid] = acc;
    __syncthreads();
    if (tid < 128) {
        const int jo = jt * 128 + tid;
        g_ypart[b * H_ + jo] = bf[jo] + psum[tid] + psum[tid + 128];
    }
}

// ---------------------------------------------------------------------------
// K6 (FINAL): merges + softmax + lru + r_curr + fixups + y tail.
// grid = 64 b x 4 jtiles = 256 blocks, 256 threads.
// ---------------------------------------------------------------------------
__global__ void k_finalyout(const float* __restrict__ Mprev, const float* __restrict__ wrp,
                            const float* __restrict__ Wf,
                            float* __restrict__ Mout, float* __restrict__ wr_out,
                            float* __restrict__ us_out, float* __restrict__ r_out,
                            float* __restrict__ y) {
    const int b = blockIdx.x >> 2;
    const int jt = blockIdx.x & 3;
    const int tid = threadIdx.x;
    const int lane = tid & 31, warp = tid >> 5;

    __shared__ u64   sw[8][4];
    __shared__ float s_p[4];
    __shared__ int   s_idx[4];
    __shared__ u64   s_uk[5];
    __shared__ int   s_lru;
    __shared__ float s_r[W_];

    {
        u64 a[4];
        a[0] = g_simk[b * 512 + tid * 2];
        a[1] = g_simk[b * 512 + tid * 2 + 1];
        a[2] = 0ull; a[3] = 0ull;
        warp_bmerge4<16>(a);
        if (lane == 0) {
#pragma unroll
            for (int jj = 0; jj < 4; jj++) sw[warp][jj] = a[jj];
        }
    }
    __syncthreads();

    if (warp == 0) {
        u64 a[4];
        if (lane < 8) {
#pragma unroll
            for (int jj = 0; jj < 4; jj++) a[jj] = sw[lane][jj];
        } else {
#pragma unroll
            for (int jj = 0; jj < 4; jj++) a[jj] = 0ull;
        }
        warp_bmerge4<4>(a);
        if (lane == 0) {
            float lv[4];
#pragma unroll
            for (int jj = 0; jj < 4; jj++) lv[jj] = key_val(a[jj]);
            float vmax = lv[0], sum = 0.0f, ev[4];
#pragma unroll
            for (int jj = 0; jj < 4; jj++) { ev[jj] = expf(lv[jj] - vmax); sum += ev[jj]; }
            float inv = 1.0f / sum;
#pragma unroll
            for (int jj = 0; jj < 4; jj++) { s_p[jj] = ev[jj] * inv; s_idx[jj] = key_idx(a[jj]); }
        }
    } else if (warp == 1 && jt == 0) {
        u64 a[5];
        a[0] = g_usk[b * 40 + lane];
        a[1] = (lane < 8) ? g_usk[b * 40 + 32 + lane] : 0ull;
        CE_DESC(a[0], a[1]);
#pragma unroll
        for (int jj = 2; jj < 5; jj++) a[jj] = 0ull;
        warp_bmerge5<16>(a);
        if (lane == 0) {
#pragma unroll
            for (int jj = 0; jj < 5; jj++) s_uk[jj] = a[jj];
        }
    }
    __syncthreads();

    if (tid >= 64 && tid < 128) {
        const int w = tid - 64;
        float r = s_p[0] * Mprev[((size_t)b * N_ + s_idx[0]) * W_ + w]
                + s_p[1] * Mprev[((size_t)b * N_ + s_idx[1]) * W_ + w]
                + s_p[2] * Mprev[((size_t)b * N_ + s_idx[2]) * W_ + w]
                + s_p[3] * Mprev[((size_t)b * N_ + s_idx[3]) * W_ + w];
        s_r[w] = r;
        if (jt == 0) r_out[b * W_ + w] = r;
    }
    if (tid == 0 && jt == 0) {
        int lru = key_idx(s_uk[0]);
#pragma unroll
        for (int jj = 0; jj < 5; jj++) {
            int c = key_idx(s_uk[jj]);
            if (c != s_idx[0] && c != s_idx[1] && c != s_idx[2] && c != s_idx[3]) { lru = c; break; }
        }
        s_lru = lru;
    }
    __syncthreads();

    if (jt == 0) {
        if (tid >= 160 && tid < 164) {
            const int jj = tid - 160;
            const int idx = s_idx[jj];
            wr_out[b * N_ + idx] = s_p[jj];
            us_out[b * N_ + idx] = 0.0f;
        }
        if (tid >= 192 && tid < 208) {
            const int k = tid - 192;
            const int lru = s_lru;
            const float alpha = g_alpha[b], gamma = g_gamma[b];
            const float ww = alpha * (gamma * wrp[b * N_ + lru] + (1.0f - gamma));
            const size_t rowoff = ((size_t)b * N_ + lru) * W_;
            float4 mrow = *(const float4*)(Mprev + rowoff + k * 4);
            float4 e4 = *(const float4*)(g_e + b * W_ + k * 4);
            float4 a4 = *(const float4*)(g_a + b * W_ + k * 4);
            float4 o;
            o.x = mrow.x * (1.0f - ww * e4.x) + ww * a4.x;
            o.y = mrow.y * (1.0f - ww * e4.y) + ww * a4.y;
            o.z = mrow.z * (1.0f - ww * e4.z) + ww * a4.z;
            o.w = mrow.w * (1.0f - ww * e4.w) + ww * a4.w;
            *(float4*)(Mout + rowoff + k * 4) = o;
        }
    }

    if (tid < 128) {
        const int j = jt * 128 + tid;
        float acc = g_ypart[b * H_ + j];
#pragma unroll 8
        for (int k = 0; k < W_; k++) acc += s_r[k] * __ldg(Wf + (H_ + k) * H_ + j);
        y[b * H_ + j] = acc;
    }
}

// ---------------------------------------------------------------------------
extern "C" void kernel_launch(void* const* d_in, const int* in_sizes, int n_in,
                              void* d_out, int out_size) {
    const float* inputs = (const float*)d_in[0];
    const float* h_prev = (const float*)d_in[1];
    const float* c_prev = (const float*)d_in[2];
    const float* M_prev = (const float*)d_in[3];
    const float* wr_prev = (const float*)d_in[4];
    const float* usage_prev = (const float*)d_in[5];
    const float* r_prev = (const float*)d_in[6];
    const float* Wk = (const float*)d_in[7];
    const float* Uk = (const float*)d_in[8];
    const float* b_lstm = (const float*)d_in[9];
    const float* Wp = (const float*)d_in[10];
    const float* bp = (const float*)d_in[11];
    const float* Wf = (const float*)d_in[12];
    const float* bf = (const float*)d_in[13];

    float* out = (float*)d_out;
    float* o_y  = out + OFF_Y;
    float* o_h  = out + OFF_H;
    float* o_c  = out + OFF_C;
    float* o_M  = out + OFF_M;
    float* o_wr = out + OFF_WR;
    float* o_us = out + OFF_US;
    float* o_r  = out + OFF_R;

    // Side stream: sel_us at t0 (usage-only), ypart after hparams (h-only).
    // Stream/events created per call, never destroyed (capture-legal, no
    // device memory).
    cudaStream_t sB;
    cudaStreamCreateWithFlags(&sB, cudaStreamNonBlocking);
    cudaEvent_t evFork, evH, evJoin;
    cudaEventCreateWithFlags(&evFork, cudaEventDisableTiming);
    cudaEventCreateWithFlags(&evH, cudaEventDisableTiming);
    cudaEventCreateWithFlags(&evJoin, cudaEventDisableTiming);

    cudaEventRecord(evFork, 0);
    cudaStreamWaitEvent(sB, evFork, 0);
    k_sel_us<<<512, 256, 0, sB>>>(usage_prev, o_wr, o_us);

    k_gemm_z<<<256, 256>>>(inputs, r_prev, h_prev, Wk, Uk);
    k_hparams<<<64, 512>>>(c_prev, b_lstm, Wp, bp, o_h, o_c);
    cudaEventRecord(evH, 0);

    cudaStreamWaitEvent(sB, evH, 0);
    k_ypart<<<256, 256, 0, sB>>>(o_h, Wf, bf);
    cudaEventRecord(evJoin, sB);

    k_fused<<<8192, 256>>>(M_prev, wr_prev, o_M);
    cudaStreamWaitEvent(0, evJoin, 0);
    k_finalyout<<<256, 256>>>(M_prev, wr_prev, Wf, o_M, o_wr, o_us, o_r, o_y);
}

// round 16
// speedup vs baseline: 1.0867x; 1.0867x over previous
#include <cuda_runtime.h>
#include <cuda_bf16.h>
#include <cstdint>
#include <cfloat>

#define B_    64
#define H_    512
#define N_    16384
#define W_    64
#define DIN_  512
#define KDIM_ 1088
#define G4_   2048
#define KSPLIT_ 16
#define KPER_   68    // 1088/16

// d_out layout (floats)
#define OFF_Y   0
#define OFF_H   32768
#define OFF_C   65536
#define OFF_M   98304
#define OFF_WR  67207168
#define OFF_US  68255744
#define OFF_R   69304320

typedef unsigned long long u64;

// scratch
__device__ float g_zp[KSPLIT_ * B_ * G4_];
__device__ float g_qn[B_ * W_];
__device__ float g_a[B_ * W_];
__device__ float g_e[B_ * W_];
__device__ float g_alpha[B_];
__device__ float g_gamma[B_];
__device__ u64   g_simk[8192 * 4];  // per fused-block top-4 sim keys
__device__ u64   g_usk[512 * 5];    // (b*8+chunk) top-5 usage keys
__device__ float g_ypart[B_ * H_];  // y partial (h-portion of the dot)

__device__ __forceinline__ float sigmoidf_(float x) { return 1.0f / (1.0f + expf(-x)); }

// ---- packed-key primitives (merge phase only) ----
__device__ __forceinline__ u64 umax64(u64 a, u64 b) { return a > b ? a : b; }
__device__ __forceinline__ u64 umin64(u64 a, u64 b) { return a < b ? a : b; }
#define CE_DESC(x, y) { u64 _mx = umax64(x, y); u64 _mn = umin64(x, y); (x) = _mx; (y) = _mn; }

__device__ __forceinline__ u64 pack_key(float v, int n) {
    unsigned vb = __float_as_uint(v);
    vb = (vb & 0x80000000u) ? ~vb : (vb | 0x80000000u);
    return ((u64)vb << 32) | (unsigned)(0xFFFFFFFFu - (unsigned)n);
}
__device__ __forceinline__ float key_val(u64 k) {
    unsigned vb = (unsigned)(k >> 32);
    vb = (vb & 0x80000000u) ? (vb ^ 0x80000000u) : ~vb;
    return __uint_as_float(vb);
}
__device__ __forceinline__ int key_idx(u64 k) {
    return (int)(0xFFFFFFFFu - (unsigned)(k & 0xFFFFFFFFull));
}

__device__ __forceinline__ void bmerge4(u64* a, const u64* brev) {
    a[0] = umax64(a[0], brev[0]); a[1] = umax64(a[1], brev[1]);
    a[2] = umax64(a[2], brev[2]); a[3] = umax64(a[3], brev[3]);
    CE_DESC(a[0], a[2]); CE_DESC(a[1], a[3]);
    CE_DESC(a[0], a[1]); CE_DESC(a[2], a[3]);
}

__device__ __forceinline__ void bmerge5(u64* a, const u64* brev) {
#pragma unroll
    for (int j = 0; j < 5; j++) a[j] = umax64(a[j], brev[j]);
#pragma unroll
    for (int i = 1; i < 5; i++)
#pragma unroll
        for (int j = i; j > 0; j--)
            CE_DESC(a[j-1], a[j]);
}

template<int MAXOFF>
__device__ __forceinline__ void warp_bmerge4(u64* a) {
#pragma unroll
    for (int off = MAXOFF; off > 0; off >>= 1) {
        u64 b[4];
#pragma unroll
        for (int j = 0; j < 4; j++) b[j] = __shfl_down_sync(0xffffffffu, a[3-j], off);
        bmerge4(a, b);
    }
}

template<int MAXOFF>
__device__ __forceinline__ void warp_bmerge5(u64* a) {
#pragma unroll
    for (int off = MAXOFF; off > 0; off >>= 1) {
        u64 b[5];
#pragma unroll
        for (int j = 0; j < 5; j++) b[j] = __shfl_down_sync(0xffffffffu, a[4-j], off);
        bmerge5(a, b);
    }
}

// ---- fp32 scan primitives ----
__device__ __forceinline__ void insf4(float* bv, int* bi, float v, int n) {
    if (v > bv[3] || (v == bv[3] && n < bi[3])) {
        bv[3] = v; bi[3] = n;
        if (bv[3] > bv[2] || (bv[3] == bv[2] && bi[3] < bi[2])) {
            float tv = bv[2]; bv[2] = bv[3]; bv[3] = tv;
            int ti = bi[2]; bi[2] = bi[3]; bi[3] = ti;
        }
        if (bv[2] > bv[1] || (bv[2] == bv[1] && bi[2] < bi[1])) {
            float tv = bv[1]; bv[1] = bv[2]; bv[2] = tv;
            int ti = bi[1]; bi[1] = bi[2]; bi[2] = ti;
        }
        if (bv[1] > bv[0] || (bv[1] == bv[0] && bi[1] < bi[0])) {
            float tv = bv[0]; bv[0] = bv[1]; bv[1] = tv;
            int ti = bi[0]; bi[0] = bi[1]; bi[1] = ti;
        }
    }
}

__device__ __forceinline__ void insf5(float* bv, int* bi, float v, int n) {
    if (v > bv[4] || (v == bv[4] && n < bi[4])) {
        bv[4] = v; bi[4] = n;
        if (bv[4] > bv[3] || (bv[4] == bv[3] && bi[4] < bi[3])) {
            float tv = bv[3]; bv[3] = bv[4]; bv[4] = tv;
            int ti = bi[3]; bi[3] = bi[4]; bi[4] = ti;
        }
        if (bv[3] > bv[2] || (bv[3] == bv[2] && bi[3] < bi[2])) {
            float tv = bv[2]; bv[2] = bv[3]; bv[3] = tv;
            int ti = bi[2]; bi[2] = bi[3]; bi[3] = ti;
        }
        if (bv[2] > bv[1] || (bv[2] == bv[1] && bi[2] < bi[1])) {
            float tv = bv[1]; bv[1] = bv[2]; bv[2] = tv;
            int ti = bi[1]; bi[1] = bi[2]; bi[2] = ti;
        }
        if (bv[1] > bv[0] || (bv[1] == bv[0] && bi[1] < bi[0])) {
            float tv = bv[0]; bv[0] = bv[1]; bv[1] = tv;
            int ti = bi[0]; bi[0] = bi[1]; bi[1] = ti;
        }
    }
}

// ---------------------------------------------------------------------------
// K1: z partials. grid = 32 j-tiles x 16 k-splits = 512 blocks, 256 threads.
// 17 chunks of 4k (R4-proven shape; half the serial work of the R14 version).
// ---------------------------------------------------------------------------
__global__ void k_gemm_z(const float* __restrict__ inp, const float* __restrict__ rprev,
                         const float* __restrict__ hprev, const float* __restrict__ Wk,
                         const float* __restrict__ Uk) {
    __shared__ __align__(16) float Xs[4][64];
    __shared__ __align__(16) float Ws[4][64];
    const int jt = blockIdx.x & 31;
    const int ks = blockIdx.x >> 5;
    const int j0 = jt * 64;
    const int kbase = ks * KPER_;
    const int t = threadIdx.x;
    const int tj = t & 15;
    const int tb = t >> 4;

    float acc[4][4];
#pragma unroll
    for (int r = 0; r < 4; r++)
#pragma unroll
        for (int c = 0; c < 4; c++) acc[r][c] = 0.0f;

    for (int cch = 0; cch < 17; cch++) {
        const int k0 = kbase + cch * 4;
        {   // X: 64b x 4k = 256 elements, one per thread
            int b = t >> 2, kk = t & 3, kg = k0 + kk;
            float v;
            if (kg < DIN_)            v = inp[b * DIN_ + kg];
            else if (kg < DIN_ + W_)  v = rprev[b * W_ + (kg - DIN_)];
            else                      v = hprev[b * H_ + (kg - DIN_ - W_)];
            Xs[kk][b] = v;
        }
        {   // W: 4k x 64j
            int kk = t >> 6, jj = t & 63, kg = k0 + kk;
            float w = (kg < DIN_ + W_) ? Wk[kg * G4_ + j0 + jj]
                                       : Uk[(kg - DIN_ - W_) * G4_ + j0 + jj];
            Ws[kk][jj] = w;
        }
        __syncthreads();
#pragma unroll
        for (int kk = 0; kk < 4; kk++) {
            float4 xv = *(const float4*)&Xs[kk][tb * 4];
            float4 wv = *(const float4*)&Ws[kk][tj * 4];
            float xr[4] = {xv.x, xv.y, xv.z, xv.w};
            float wc[4] = {wv.x, wv.y, wv.z, wv.w};
#pragma unroll
            for (int r = 0; r < 4; r++)
#pragma unroll
                for (int c = 0; c < 4; c++) acc[r][c] += xr[r] * wc[c];
        }
        __syncthreads();
    }
#pragma unroll
    for (int r = 0; r < 4; r++) {
        float4 st = make_float4(acc[r][0], acc[r][1], acc[r][2], acc[r][3]);
        *(float4*)&g_zp[ks * (B_ * G4_) + (tb * 4 + r) * G4_ + j0 + tj * 4] = st;
    }
}

// ---------------------------------------------------------------------------
// K2: z reduce (16-way) + gates + params + derive. grid=64 (b), block=512
// ---------------------------------------------------------------------------
__global__ void k_hparams(const float* __restrict__ cprev, const float* __restrict__ bl,
                          const float* __restrict__ Wp, const float* __restrict__ bp,
                          float* __restrict__ h_out, float* __restrict__ c_out) {
    __shared__ float zz[G4_];
    __shared__ float sh[H_];
    __shared__ float sp[194];
    __shared__ float ws[2];
    const int b = blockIdx.x, tid = threadIdx.x;

#pragma unroll
    for (int i = 0; i < 4; i++) {
        const int hh = tid + i * 512;
        float z = bl[hh];
#pragma unroll
        for (int ks = 0; ks < KSPLIT_; ks++)
            z += g_zp[ks * (B_ * G4_) + b * G4_ + hh];
        zz[hh] = z;
    }
    __syncthreads();

    {
        const int hh = tid;
        float ig = sigmoidf_(zz[hh]);
        float fg = sigmoidf_(zz[H_ + hh]);
        float og = sigmoidf_(zz[3 * H_ + hh]);
        float c  = fg * cprev[b * H_ + hh] + ig * tanhf(zz[2 * H_ + hh]);
        float h  = og * tanhf(c);
        c_out[b * H_ + hh] = c;
        h_out[b * H_ + hh] = h;
        sh[hh] = h;
    }
    __syncthreads();

    if (tid < 194) {
        float acc = bp[tid];
#pragma unroll 8
        for (int k = 0; k < H_; k++) acc += sh[k] * Wp[k * 194 + tid];
        sp[tid] = acc;
    }
    __syncthreads();

    if (tid < 64) {
        float q = sp[tid];
        float s = q * q;
#pragma unroll
        for (int off = 16; off > 0; off >>= 1) s += __shfl_down_sync(0xffffffffu, s, off);
        if ((tid & 31) == 0) ws[tid >> 5] = s;
    }
    __syncthreads();
    if (tid < 64) {
        float tot = ws[0] + ws[1];
        g_qn[b * W_ + tid] = sp[tid] * rsqrtf(fmaxf(tot, 1e-12f));
        g_a[b * W_ + tid]  = sp[W_ + tid];
        g_e[b * W_ + tid]  = sigmoidf_(sp[2 * W_ + tid]);
        if (tid == 0) {
            g_alpha[b] = sigmoidf_(sp[192]);
            g_gamma[b] = sigmoidf_(sp[193]);
        }
    }
}

// ---------------------------------------------------------------------------
// K3 (FUSED, frozen R11/R14 form)
// ---------------------------------------------------------------------------
__global__ void k_fused(const float* __restrict__ M, const float* __restrict__ wrp,
                        float* __restrict__ Mout) {
    const int b  = blockIdx.x >> 7;
    const int n0 = (blockIdx.x & 127) << 7;
    const int tid = threadIdx.x;
    __shared__ __align__(16) float se[W_], sa[W_], sq[W_];
    __shared__ __align__(16) float s_sim[128];
    __shared__ float s_ag;
    if (tid < W_) { se[tid] = g_e[b * W_ + tid]; sa[tid] = g_a[b * W_ + tid]; sq[tid] = g_qn[b * W_ + tid]; }
    if (tid == 0) s_ag = g_alpha[b] * g_gamma[b];
    __syncthreads();

    const int lane = tid & 31, warp = tid >> 5;
    const int half = lane >> 4, l16 = lane & 15;
    const int rbase = warp * 2 + half;
    const size_t browoff = (size_t)b * N_ + n0;

    float4 m[8];
    float wr[8];
#pragma unroll
    for (int i = 0; i < 8; i++)
        m[i] = __ldcs((const float4*)(M + (browoff + i * 16 + rbase) * W_) + l16);
#pragma unroll
    for (int i = 0; i < 8; i++)
        wr[i] = __ldg(wrp + browoff + i * 16 + rbase);

    const float4 e4 = *(const float4*)(se + l16 * 4);
    const float4 a4 = *(const float4*)(sa + l16 * 4);
    const float4 q4 = *(const float4*)(sq + l16 * 4);
    const float ag = s_ag;

#pragma unroll
    for (int i = 0; i < 8; i++) {
        float dot = m[i].x * q4.x + m[i].y * q4.y + m[i].z * q4.z + m[i].w * q4.w;
        float ss  = m[i].x * m[i].x + m[i].y * m[i].y + m[i].z * m[i].z + m[i].w * m[i].w;
#pragma unroll
        for (int off = 8; off > 0; off >>= 1) {
            dot += __shfl_down_sync(0xffffffffu, dot, off);
            ss  += __shfl_down_sync(0xffffffffu, ss,  off);
        }
        if (l16 == 0) s_sim[i * 16 + rbase] = dot * rsqrtf(fmaxf(ss, 1e-12f));

        const float ww = ag * wr[i];
        float4 o;
        o.x = m[i].x * (1.0f - ww * e4.x) + ww * a4.x;
        o.y = m[i].y * (1.0f - ww * e4.y) + ww * a4.y;
        o.z = m[i].z * (1.0f - ww * e4.z) + ww * a4.z;
        o.w = m[i].w * (1.0f - ww * e4.w) + ww * a4.w;
        __stcs((float4*)(Mout + (browoff + i * 16 + rbase) * W_) + l16, o);
    }
    __syncthreads();

    if (warp == 0) {
        float4 sv = ((const float4*)s_sim)[lane];
        float bv[4] = {-FLT_MAX, -FLT_MAX, -FLT_MAX, -FLT_MAX};
        int   bi[4] = {0x7FFFFFFF, 0x7FFFFFFF, 0x7FFFFFFF, 0x7FFFFFFF};
        const int nb = n0 + lane * 4;
        insf4(bv, bi, sv.x, nb + 0);
        insf4(bv, bi, sv.y, nb + 1);
        insf4(bv, bi, sv.z, nb + 2);
        insf4(bv, bi, sv.w, nb + 3);
        u64 a[4];
#pragma unroll
        for (int j = 0; j < 4; j++) a[j] = pack_key(bv[j], bi[j]);
        warp_bmerge4<16>(a);
        if (lane == 0) {
#pragma unroll
            for (int j = 0; j < 4; j++) g_simk[blockIdx.x * 4 + j] = a[j];
        }
    }
}

// ---------------------------------------------------------------------------
// K4 (side stream): usage top-5 + us/wr streams. grid=512, block=256.
// ---------------------------------------------------------------------------
__global__ void k_sel_us(const float* __restrict__ usprev,
                         float* __restrict__ wr_out, float* __restrict__ us_out) {
    const int tid = threadIdx.x;
    const int lane = tid & 31, warp = tid >> 5;
    const int b = blockIdx.x >> 3, chunk = blockIdx.x & 7;
    const int base = b * N_ + chunk * 2048;
    const float4* usb = (const float4*)(usprev + base);
    float4* uso = (float4*)(us_out + base);
    float4* wro = (float4*)(wr_out + base);
    const int nbase = chunk * 2048;

    float bv[5] = {-FLT_MAX, -FLT_MAX, -FLT_MAX, -FLT_MAX, -FLT_MAX};
    int   bi[5] = {0x7FFFFFFF, 0x7FFFFFFF, 0x7FFFFFFF, 0x7FFFFFFF, 0x7FFFFFFF};

    float4 v0 = __ldg(usb + tid);
    float4 v1 = __ldg(usb + 256 + tid);
    __stcs(uso + tid,       make_float4(v0.x + 1.f, v0.y + 1.f, v0.z + 1.f, v0.w + 1.f));
    __stcs(uso + 256 + tid, make_float4(v1.x + 1.f, v1.y + 1.f, v1.z + 1.f, v1.w + 1.f));
    __stcs(wro + tid,       make_float4(0.f, 0.f, 0.f, 0.f));
    __stcs(wro + 256 + tid, make_float4(0.f, 0.f, 0.f, 0.f));

    insf5(bv, bi, v0.x, nbase + tid * 4 + 0);
    insf5(bv, bi, v0.y, nbase + tid * 4 + 1);
    insf5(bv, bi, v0.z, nbase + tid * 4 + 2);
    insf5(bv, bi, v0.w, nbase + tid * 4 + 3);
    insf5(bv, bi, v1.x, nbase + 1024 + tid * 4 + 0);
    insf5(bv, bi, v1.y, nbase + 1024 + tid * 4 + 1);
    insf5(bv, bi, v1.z, nbase + 1024 + tid * 4 + 2);
    insf5(bv, bi, v1.w, nbase + 1024 + tid * 4 + 3);

    u64 a[5];
#pragma unroll
    for (int j = 0; j < 5; j++) a[j] = pack_key(bv[j], bi[j]);
    warp_bmerge5<16>(a);

    __shared__ u64 sw5[8][5];
    if (lane == 0) {
#pragma unroll
        for (int j = 0; j < 5; j++) sw5[warp][j] = a[j];
    }
    __syncthreads();
    if (warp == 0) {
        if (lane < 8) {
#pragma unroll
            for (int j = 0; j < 5; j++) a[j] = sw5[lane][j];
        } else {
#pragma unroll
            for (int j = 0; j < 5; j++) a[j] = 0ull;
        }
        warp_bmerge5<4>(a);
        if (lane == 0) {
#pragma unroll
            for (int j = 0; j < 5; j++) g_usk[blockIdx.x * 5 + j] = a[j];
        }
    }
}

// ---------------------------------------------------------------------------
// K5 (side stream, after hparams): y partial = bf + h @ Wf[0:512].
// ---------------------------------------------------------------------------
__global__ void k_ypart(const float* __restrict__ h, const float* __restrict__ Wf,
                        const float* __restrict__ bf) {
    __shared__ __align__(16) float xs[H_];
    __shared__ float psum[256];
    const int b = blockIdx.x >> 2;
    const int jt = blockIdx.x & 3;
    const int tid = threadIdx.x;

    xs[tid]       = h[b * H_ + tid];
    xs[tid + 256] = h[b * H_ + tid + 256];
    __syncthreads();

    const int jl = tid & 127;
    const int j = jt * 128 + jl;
    const int khalf = tid >> 7;
    float acc = 0.0f;
    const int k0 = khalf * 256, k1 = k0 + 256;
#pragma unroll 8
    for (int k = k0; k < k1; k++) acc += xs[k] * __ldg(Wf + k * H_ + j);
    psum[tid] = acc;
    __syncthreads();
    if (tid < 128) {
        const int jo = jt * 128 + tid;
        g_ypart[b * H_ + jo] = bf[jo] + psum[tid] + psum[tid + 128];
    }
}

// ---------------------------------------------------------------------------
// K6 (FINAL): merges + softmax + lru + r_curr + fixups + y tail.
// grid = 64 b x 4 jtiles = 256 blocks, 256 threads.
// ---------------------------------------------------------------------------
__global__ void k_finalyout(const float* __restrict__ Mprev, const float* __restrict__ wrp,
                            const float* __restrict__ Wf,
                            float* __restrict__ Mout, float* __restrict__ wr_out,
                            float* __restrict__ us_out, float* __restrict__ r_out,
                            float* __restrict__ y) {
    const int b = blockIdx.x >> 2;
    const int jt = blockIdx.x & 3;
    const int tid = threadIdx.x;
    const int lane = tid & 31, warp = tid >> 5;

    __shared__ u64   sw[8][4];
    __shared__ float s_p[4];
    __shared__ int   s_idx[4];
    __shared__ u64   s_uk[5];
    __shared__ int   s_lru;
    __shared__ float s_r[W_];

    {
        u64 a[4];
        a[0] = g_simk[b * 512 + tid * 2];
        a[1] = g_simk[b * 512 + tid * 2 + 1];
        a[2] = 0ull; a[3] = 0ull;
        warp_bmerge4<16>(a);
        if (lane == 0) {
#pragma unroll
            for (int jj = 0; jj < 4; jj++) sw[warp][jj] = a[jj];
        }
    }
    __syncthreads();

    if (warp == 0) {
        u64 a[4];
        if (lane < 8) {
#pragma unroll
            for (int jj = 0; jj < 4; jj++) a[jj] = sw[lane][jj];
        } else {
#pragma unroll
            for (int jj = 0; jj < 4; jj++) a[jj] = 0ull;
        }
        warp_bmerge4<4>(a);
        if (lane == 0) {
            float lv[4];
#pragma unroll
            for (int jj = 0; jj < 4; jj++) lv[jj] = key_val(a[jj]);
            float vmax = lv[0], sum = 0.0f, ev[4];
#pragma unroll
            for (int jj = 0; jj < 4; jj++) { ev[jj] = expf(lv[jj] - vmax); sum += ev[jj]; }
            float inv = 1.0f / sum;
#pragma unroll
            for (int jj = 0; jj < 4; jj++) { s_p[jj] = ev[jj] * inv; s_idx[jj] = key_idx(a[jj]); }
        }
    } else if (warp == 1 && jt == 0) {
        u64 a[5];
        a[0] = g_usk[b * 40 + lane];
        a[1] = (lane < 8) ? g_usk[b * 40 + 32 + lane] : 0ull;
        CE_DESC(a[0], a[1]);
#pragma unroll
        for (int jj = 2; jj < 5; jj++) a[jj] = 0ull;
        warp_bmerge5<16>(a);
        if (lane == 0) {
#pragma unroll
            for (int jj = 0; jj < 5; jj++) s_uk[jj] = a[jj];
        }
    }
    __syncthreads();

    if (tid >= 64 && tid < 128) {
        const int w = tid - 64;
        float r = s_p[0] * Mprev[((size_t)b * N_ + s_idx[0]) * W_ + w]
                + s_p[1] * Mprev[((size_t)b * N_ + s_idx[1]) * W_ + w]
                + s_p[2] * Mprev[((size_t)b * N_ + s_idx[2]) * W_ + w]
                + s_p[3] * Mprev[((size_t)b * N_ + s_idx[3]) * W_ + w];
        s_r[w] = r;
        if (jt == 0) r_out[b * W_ + w] = r;
    }
    if (tid == 0 && jt == 0) {
        int lru = key_idx(s_uk[0]);
#pragma unroll
        for (int jj = 0; jj < 5; jj++) {
            int c = key_idx(s_uk[jj]);
            if (c != s_idx[0] && c != s_idx[1] && c != s_idx[2] && c != s_idx[3]) { lru = c; break; }
        }
        s_lru = lru;
    }
    __syncthreads();

    if (jt == 0) {
        if (tid >= 160 && tid < 164) {
            const int jj = tid - 160;
            const int idx = s_idx[jj];
            wr_out[b * N_ + idx] = s_p[jj];
            us_out[b * N_ + idx] = 0.0f;
        }
        if (tid >= 192 && tid < 208) {
            const int k = tid - 192;
            const int lru = s_lru;
            const float alpha = g_alpha[b], gamma = g_gamma[b];
            const float ww = alpha * (gamma * wrp[b * N_ + lru] + (1.0f - gamma));
            const size_t rowoff = ((size_t)b * N_ + lru) * W_;
            float4 mrow = *(const float4*)(Mprev + rowoff + k * 4);
            float4 e4 = *(const float4*)(g_e + b * W_ + k * 4);
            float4 a4 = *(const float4*)(g_a + b * W_ + k * 4);
            float4 o;
            o.x = mrow.x * (1.0f - ww * e4.x) + ww * a4.x;
            o.y = mrow.y * (1.0f - ww * e4.y) + ww * a4.y;
            o.z = mrow.z * (1.0f - ww * e4.z) + ww * a4.z;
            o.w = mrow.w * (1.0f - ww * e4.w) + ww * a4.w;
            *(float4*)(Mout + rowoff + k * 4) = o;
        }
    }

    if (tid < 128) {
        const int j = jt * 128 + tid;
        float acc = g_ypart[b * H_ + j];
#pragma unroll 8
        for (int k = 0; k < W_; k++) acc += s_r[k] * __ldg(Wf + (H_ + k) * H_ + j);
        y[b * H_ + j] = acc;
    }
}

// ---------------------------------------------------------------------------
extern "C" void kernel_launch(void* const* d_in, const int* in_sizes, int n_in,
                              void* d_out, int out_size) {
    const float* inputs = (const float*)d_in[0];
    const float* h_prev = (const float*)d_in[1];
    const float* c_prev = (const float*)d_in[2];
    const float* M_prev = (const float*)d_in[3];
    const float* wr_prev = (const float*)d_in[4];
    const float* usage_prev = (const float*)d_in[5];
    const float* r_prev = (const float*)d_in[6];
    const float* Wk = (const float*)d_in[7];
    const float* Uk = (const float*)d_in[8];
    const float* b_lstm = (const float*)d_in[9];
    const float* Wp = (const float*)d_in[10];
    const float* bp = (const float*)d_in[11];
    const float* Wf = (const float*)d_in[12];
    const float* bf = (const float*)d_in[13];

    float* out = (float*)d_out;
    float* o_y  = out + OFF_Y;
    float* o_h  = out + OFF_H;
    float* o_c  = out + OFF_C;
    float* o_M  = out + OFF_M;
    float* o_wr = out + OFF_WR;
    float* o_us = out + OFF_US;
    float* o_r  = out + OFF_R;

    // Side stream: sel_us at t0 (usage-only), ypart after hparams (h-only).
    // Stream/events created per call, never destroyed (capture-legal, no
    // device memory).
    cudaStream_t sB;
    cudaStreamCreateWithFlags(&sB, cudaStreamNonBlocking);
    cudaEvent_t evFork, evH, evJoin;
    cudaEventCreateWithFlags(&evFork, cudaEventDisableTiming);
    cudaEventCreateWithFlags(&evH, cudaEventDisableTiming);
    cudaEventCreateWithFlags(&evJoin, cudaEventDisableTiming);

    cudaEventRecord(evFork, 0);
    cudaStreamWaitEvent(sB, evFork, 0);
    k_sel_us<<<512, 256, 0, sB>>>(usage_prev, o_wr, o_us);

    k_gemm_z<<<512, 256>>>(inputs, r_prev, h_prev, Wk, Uk);
    k_hparams<<<64, 512>>>(c_prev, b_lstm, Wp, bp, o_h, o_c);
    cudaEventRecord(evH, 0);

    cudaStreamWaitEvent(sB, evH, 0);
    k_ypart<<<256, 256, 0, sB>>>(o_h, Wf, bf);
    cudaEventRecord(evJoin, sB);

    k_fused<<<8192, 256>>>(M_prev, wr_prev, o_M);
    cudaStreamWaitEvent(0, evJoin, 0);
    k_finalyout<<<256, 256>>>(M_prev, wr_prev, Wf, o_M, o_wr, o_us, o_r, o_y);
}